// round 13
// baseline (speedup 1.0000x reference)
#include <cuda_runtime.h>
#include <cuda_fp16.h>
#include <cstdint>
#include <math.h>

#define NN 10000
#define EE 160000
#define TE 128
#define THREADS 512

// ---- shared memory byte offsets ----
#define SM_BH  0         // 256 rows x 64 fp16 (128B rows), SW128
#define SM_AH  32768     // 128 rows x 64 fp16 (128B rows), SW128
#define SM_C   49152     // 128 x 132 fp32 (padded rows) = 67584B
#define SM_XT  116736    // 64 x 128 fp32 = 32768B
#define SM_EMB 149504    // 128 x 16 fp32
#define SM_W1  157696    // 16 x 64 fp32
#define SM_B1  161792    // 64 fp32
#define SM_B2P 162048    // 256 fp32 (permuted quadrant bias)
#define SM_SH  163072    // 128 x 4 fp32
#define SM_SRC 165120    // 128 int
#define SM_DST 165632    // 128 int
#define SMEM_TOTAL 166144

#define SW128(x) ((x) ^ (((x) >> 3) & 0x70))
#define CPAD 132

__device__ float g_agg[NN * 64];

static __device__ __forceinline__ uint32_t smem_u32(const void* p) {
    uint32_t a;
    asm("{ .reg .u64 t; cvta.to.shared.u64 t, %1; cvt.u32.u64 %0, t; }" : "=r"(a) : "l"(p));
    return a;
}

#define LDSM4(r0, r1, r2, r3, addr) \
    asm volatile("ldmatrix.sync.aligned.m8n8.x4.shared.b16 {%0,%1,%2,%3}, [%4];" \
                 : "=r"(r0), "=r"(r1), "=r"(r2), "=r"(r3) : "r"(addr))

#define MMA16816(d, a, b0, b1) \
    asm volatile("mma.sync.aligned.m16n8k16.row.col.f32.f16.f16.f32 " \
                 "{%0,%1,%2,%3}, {%4,%5,%6,%7}, {%8,%9}, {%0,%1,%2,%3};" \
                 : "+f"((d)[0]), "+f"((d)[1]), "+f"((d)[2]), "+f"((d)[3]) \
                 : "r"((a)[0]), "r"((a)[1]), "r"((a)[2]), "r"((a)[3]), "r"(b0), "r"(b1))

__global__ __launch_bounds__(THREADS, 1)
void edge_kernel(const float* __restrict__ nf,
                 const float* __restrict__ esh,
                 const float* __restrict__ emb,
                 const float* __restrict__ w1,
                 const float* __restrict__ b1,
                 const float* __restrict__ w2,
                 const float* __restrict__ b2,
                 const int*   __restrict__ eidx)
{
    extern __shared__ __align__(1024) char sm[];
    const uint32_t sbase = smem_u32(sm);

    const int t = threadIdx.x;
    const int wid = t >> 5, lid = t & 31;
    const int qd = blockIdx.x & 3;           // v-quarter role 0..3

    float* sC   = (float*)(sm + SM_C);
    float* sXT  = (float*)(sm + SM_XT);
    float* sEmb = (float*)(sm + SM_EMB);
    float* sW1  = (float*)(sm + SM_W1);
    float* sB1  = (float*)(sm + SM_B1);
    float* sB2P = (float*)(sm + SM_B2P);
    float* sSH  = (float*)(sm + SM_SH);
    int*   sSrc = (int*)(sm + SM_SRC);
    int*   sDst = (int*)(sm + SM_DST);

    // ---- one-time staging ----
    // B physical row p = b*64 + vl*16 + u  ->  w2 col n = b*256 + u*16 + (qd*4+vl)
    for (int idx = t; idx < 64 * 256; idx += THREADS) {
        int k = idx >> 8, p = idx & 255;
        int b = p >> 6, vl = (p >> 4) & 3, u = p & 15;
        int n = b * 256 + u * 16 + qd * 4 + vl;
        float w = w2[k * 1024 + n];
        uint32_t off = SW128((uint32_t)(p * 128 + k * 2));
        *(__half*)(sm + SM_BH + off) = __float2half(w);
    }
    if (t < 256) {
        int p = t;
        int b = p >> 6, vl = (p >> 4) & 3, u = p & 15;
        sB2P[p] = b2[b * 256 + u * 16 + qd * 4 + vl];
    }
    for (int i = t; i < 1024; i += THREADS) sW1[i] = w1[i];
    if (t < 64) sB1[t] = b1[t];
    __syncthreads();

    const float ALPHA = 0.17677669529663687f;   // 1/sqrt(2*16)
    const float INV3  = 0.5773502691896258f;    // 1/sqrt(3)

    // MMA warp tiling: warp tile 32e x 32p per chunk
    const int wy = wid & 3;                    // e block
    const int wx = wid >> 2;                   // p block within chunk
    const int mi = lid >> 3, r = lid & 7;
    const int a_row_base = wy * 32 + ((mi & 1) << 3) + r;
    const uint32_t a_kb = (uint32_t)((mi >> 1) << 4);
    const int b_row_off = ((mi >> 1) << 3) + r;
    const uint32_t b_kb = (uint32_t)((mi & 1) << 4);
    const uint32_t lmask = (uint32_t)(r << 4);
    const int gid = lid >> 2, tid4 = lid & 3;

    // contraction mapping: e = t&127, vl = t>>7
    const int ce = t & 127;
    const int cvl = t >> 7;

    for (int tile = blockIdx.x >> 2; tile < EE / TE; tile += 37) {
        const int e0 = tile * TE;

        // ---- phase 0: stage edge meta (overlaps prior tile's reg-only scatter) ----
        if (t < 128)      sSrc[t] = eidx[e0 + t];
        else if (t < 256) sDst[t - 128] = eidx[EE + e0 + (t - 128)];
        sSH[t] = esh[e0 * 4 + t];
        #pragma unroll
        for (int rr = 0; rr < 4; ++rr) sEmb[t + rr * THREADS] = emb[e0 * 16 + t + rr * THREADS];
        __syncthreads();                                   // barA

        const int dst = sDst[ce];
        const float sh0 = sSH[ce * 4 + 0], sh1 = sSH[ce * 4 + 1];
        const float sh2 = sSH[ce * 4 + 2], sh3 = sSH[ce * 4 + 3];

        // ---- phase 1a: stage x vectors ----
        // row<16: xs[u]; row>=16: xv[u][i] at row 16 + i*16 + u
        {
            int e = t >> 2, q4 = t & 3;
            int src = sSrc[e];
            #pragma unroll
            for (int b = 0; b < 4; ++b) {
                float4 x4 = *(const float4*)(nf + src * 64 + q4 * 16 + b * 4);
                float vals[4] = {x4.x, x4.y, x4.z, x4.w};
                #pragma unroll
                for (int j = 0; j < 4; ++j) {
                    int m = q4 * 16 + b * 4 + j;           // 0..63
                    int row;
                    if (m < 16) row = m;
                    else { int mm = m - 16; row = 16 + (mm % 3) * 16 + (mm / 3); }
                    sXT[row * 128 + e] = vals[j];
                }
            }
        }

        // ---- phase 1b: H = silu(emb@w1+b1) -> fp16 A tile (SW128) ----
        #pragma unroll
        for (int rr = 0; rr < 8; ++rr) {
            int task = t + rr * THREADS;            // 4096 = 128e x 32 j-pairs
            int e = task >> 5, jp = task & 31;
            const float* er = sEmb + e * 16;
            float a0 = sB1[2 * jp], a1 = sB1[2 * jp + 1];
            #pragma unroll
            for (int k = 0; k < 16; ++k) {
                float ev = er[k];
                float2 wv = *(const float2*)(sW1 + k * 64 + 2 * jp);
                a0 += ev * wv.x;
                a1 += ev * wv.y;
            }
            float h0 = a0 / (1.0f + __expf(-a0));
            float h1 = a1 / (1.0f + __expf(-a1));
            __half2 hh = __floats2half2_rn(h0, h1);
            uint32_t off = SW128((uint32_t)(e * 128 + jp * 4));
            *(uint32_t*)(sm + SM_AH + off) = *(uint32_t*)&hh;
        }
        __syncthreads();                                   // barB

        float y00 = 0.0f, y01 = 0.0f;
        float z10_0 = 0.0f, z10_1 = 0.0f, z10_2 = 0.0f;
        float z11_0 = 0.0f, z11_1 = 0.0f, z11_2 = 0.0f;

        #pragma unroll 1
        for (int c = 0; c < 2; ++c) {
            const int cbase = c << 7;

            // ---- MMA chunk c (single-pass fp16) ----
            float acc[2][4][4];
            #pragma unroll
            for (int m = 0; m < 2; ++m)
                #pragma unroll
                for (int nt = 0; nt < 4; ++nt)
                    #pragma unroll
                    for (int z = 0; z < 4; ++z) acc[m][nt][z] = 0.0f;

            #pragma unroll
            for (int ks = 0; ks < 4; ++ks) {
                const uint32_t kx = (uint32_t)(ks * 32);
                uint32_t ah[2][4], bh[2][4];
                #pragma unroll
                for (int m = 0; m < 2; ++m) {
                    uint32_t row = (uint32_t)(a_row_base + m * 16);
                    uint32_t ad = sbase + SM_AH + row * 128 + ((kx + a_kb) ^ lmask);
                    LDSM4(ah[m][0], ah[m][1], ah[m][2], ah[m][3], ad);
                }
                #pragma unroll
                for (int pr = 0; pr < 2; ++pr) {
                    uint32_t p = (uint32_t)(cbase + wx * 32 + pr * 16 + b_row_off);
                    uint32_t bd = sbase + SM_BH + p * 128 + ((kx + b_kb) ^ lmask);
                    LDSM4(bh[pr][0], bh[pr][1], bh[pr][2], bh[pr][3], bd);
                }
                #pragma unroll
                for (int m = 0; m < 2; ++m)
                    #pragma unroll
                    for (int pr = 0; pr < 2; ++pr)
                        #pragma unroll
                        for (int sb = 0; sb < 2; ++sb)
                            MMA16816(acc[m][pr * 2 + sb], ah[m],
                                     bh[pr][sb * 2], bh[pr][sb * 2 + 1]);
            }

            // ---- store C + bias to smem (padded rows) ----
            #pragma unroll
            for (int m = 0; m < 2; ++m)
                #pragma unroll
                for (int nt = 0; nt < 4; ++nt) {
                    int colp = wx * 32 + nt * 8 + tid4 * 2;
                    float b0 = sB2P[cbase + colp], b1v = sB2P[cbase + colp + 1];
                    int row0 = wy * 32 + m * 16 + gid;
                    float2 v01 = make_float2(acc[m][nt][0] + b0, acc[m][nt][1] + b1v);
                    float2 v23 = make_float2(acc[m][nt][2] + b0, acc[m][nt][3] + b1v);
                    *(float2*)&sC[row0 * CPAD + colp] = v01;
                    *(float2*)&sC[(row0 + 8) * CPAD + colp] = v23;
                }
            __syncthreads();                               // barC / barE

            // ---- partial contraction: chunk0 -> y00,y01; chunk1 -> z10,z11 ----
            {
                const float* cA = sC + ce * CPAD + cvl * 16;        // b = 2c
                const float* cB = cA + 64;                           // b = 2c+1
                if (c == 0) {
                    #pragma unroll
                    for (int u = 0; u < 16; ++u) {
                        float xs = sXT[u * 128 + ce];
                        y00 += xs * cA[u];
                        y01 += xs * cB[u];
                    }
                } else {
                    #pragma unroll
                    for (int u = 0; u < 16; ++u) {
                        float w10 = cA[u], w11 = cB[u];
                        float x0 = sXT[(16 + 0 * 16 + u) * 128 + ce];
                        float x1 = sXT[(16 + 1 * 16 + u) * 128 + ce];
                        float x2 = sXT[(16 + 2 * 16 + u) * 128 + ce];
                        z10_0 += x0 * w10;  z11_0 += x0 * w11;
                        z10_1 += x1 * w10;  z11_1 += x1 * w11;
                        z10_2 += x2 * w10;  z11_2 += x2 * w11;
                    }
                }
            }
            if (c == 0) __syncthreads();                   // barD (sC reuse)
        }

        // ---- combined scatter: 4 atomics per (e, v), registers only ----
        {
            int v = qd * 4 + cvl;
            float msg_s = ALPHA * (sh0 * y00 + INV3 * (sh1 * z11_0 + sh2 * z11_1 + sh3 * z11_2));
            atomicAdd(&g_agg[dst * 64 + v], msg_s);
            atomicAdd(&g_agg[dst * 64 + 16 + v * 3 + 0], ALPHA * (y01 * sh1 + sh0 * z10_0));
            atomicAdd(&g_agg[dst * 64 + 16 + v * 3 + 1], ALPHA * (y01 * sh2 + sh0 * z10_1));
            atomicAdd(&g_agg[dst * 64 + 16 + v * 3 + 2], ALPHA * (y01 * sh3 + sh0 * z10_2));
        }
        // no trailing barrier: scatter is reg-only; next phase 0 smem writes are safe
    }
}

__global__ __launch_bounds__(256)
void node_kernel(const float* __restrict__ nf,
                 const float* __restrict__ lw0,
                 const float* __restrict__ lw1,
                 float* __restrict__ out)
{
    __shared__ float sw0[256], sw1[256];
    int t = threadIdx.x;
    sw0[t] = lw0[t];
    sw1[t] = lw1[t];
    __syncthreads();

    int node = blockIdx.x * 16 + (t >> 4);
    int v = t & 15;
    float* a = g_agg + node * 64;

    float ts = 0.0f, t0 = 0.0f, t1 = 0.0f, t2 = 0.0f;
    #pragma unroll
    for (int u = 0; u < 16; ++u) {
        float c0 = sw0[u * 16 + v];
        float c1 = sw1[u * 16 + v];
        ts += a[u] * c0;
        t0 += a[16 + u * 3 + 0] * c1;
        t1 += a[16 + u * 3 + 1] * c1;
        t2 += a[16 + u * 3 + 2] * c1;
    }
    __syncthreads();   // all threads of this block done reading these 16 nodes
    // re-zero for the next graph replay (g_agg starts zeroed at module load)
    a[v] = 0.0f;
    a[16 + v * 3 + 0] = 0.0f;
    a[16 + v * 3 + 1] = 0.0f;
    a[16 + v * 3 + 2] = 0.0f;

    const float S = 0.25f, EPS = 1e-8f;
    ts *= S; t0 *= S; t1 *= S; t2 *= S;

    float ns = fabsf(ts);
    float gs = ns / ((ns + EPS) * (1.0f + __expf(-ns)));
    float nv = sqrtf(t0 * t0 + t1 * t1 + t2 * t2);
    float gv = nv / ((nv + EPS) * (1.0f + __expf(-nv)));

    int base = node * 64;
    out[base + v] = nf[base + v] + ts * gs;
    out[base + 16 + v * 3 + 0] = nf[base + 16 + v * 3 + 0] + t0 * gv;
    out[base + 16 + v * 3 + 1] = nf[base + 16 + v * 3 + 1] + t1 * gv;
    out[base + 16 + v * 3 + 2] = nf[base + 16 + v * 3 + 2] + t2 * gv;
}

extern "C" void kernel_launch(void* const* d_in, const int* in_sizes, int n_in,
                              void* d_out, int out_size)
{
    const float* nf   = (const float*)d_in[0];
    const float* esh  = (const float*)d_in[1];
    const float* emb  = (const float*)d_in[2];
    const float* w1   = (const float*)d_in[3];
    const float* b1   = (const float*)d_in[4];
    const float* w2   = (const float*)d_in[5];
    const float* b2   = (const float*)d_in[6];
    const float* lw0  = (const float*)d_in[7];
    const float* lw1  = (const float*)d_in[8];
    const int*   eidx = (const int*)d_in[9];
    float* out = (float*)d_out;

    cudaFuncSetAttribute(edge_kernel, cudaFuncAttributeMaxDynamicSharedMemorySize, SMEM_TOTAL);

    // g_agg: zeroed at module load; node_kernel re-zeros after reading each call.
    edge_kernel<<<148, THREADS, SMEM_TOTAL>>>(nf, esh, emb, w1, b1, w2, b2, eidx);
    node_kernel<<<625, 256>>>(nf, lw0, lw1, out);
}

// round 14
// speedup vs baseline: 1.5586x; 1.5586x over previous
#include <cuda_runtime.h>
#include <cuda_fp16.h>
#include <cstdint>
#include <math.h>

#define NN 10000
#define EE 160000
#define TE 128
#define THREADS 512

// ---- shared memory byte offsets ----
#define SM_BH  0         // 256 rows x 64 fp16 (128B rows), SW128
#define SM_AH  32768     // 128 rows x 64 fp16 (128B rows), SW128
#define SM_C   49152     // 128 x 260 fp32 (padded rows) = 133120B
#define SM_XT  182272    // 64 x 128 fp32 = 32768B
#define SM_EMB 215040    // 128 x 16 fp32 = 8192B
#define SM_W1  223232    // 16 x 64 fp32 = 4096B
#define SM_B1  227328    // 64 fp32
#define SM_B2P 227584    // 256 fp32 (permuted bias)
#define SM_SH  228608    // 128 x 4 fp32
#define SM_SRC 230656    // 128 int
#define SM_DST 231168    // 128 int
#define SMEM_TOTAL 231680

#define SW128(x) ((x) ^ (((x) >> 3) & 0x70))
#define CPAD 260

__device__ float g_agg[NN * 64];

static __device__ __forceinline__ uint32_t smem_u32(const void* p) {
    uint32_t a;
    asm("{ .reg .u64 t; cvta.to.shared.u64 t, %1; cvt.u32.u64 %0, t; }" : "=r"(a) : "l"(p));
    return a;
}

#define LDSM4(r0, r1, r2, r3, addr) \
    asm volatile("ldmatrix.sync.aligned.m8n8.x4.shared.b16 {%0,%1,%2,%3}, [%4];" \
                 : "=r"(r0), "=r"(r1), "=r"(r2), "=r"(r3) : "r"(addr))

#define MMA16816(d, a, b0, b1) \
    asm volatile("mma.sync.aligned.m16n8k16.row.col.f32.f16.f16.f32 " \
                 "{%0,%1,%2,%3}, {%4,%5,%6,%7}, {%8,%9}, {%0,%1,%2,%3};" \
                 : "+f"((d)[0]), "+f"((d)[1]), "+f"((d)[2]), "+f"((d)[3]) \
                 : "r"((a)[0]), "r"((a)[1]), "r"((a)[2]), "r"((a)[3]), "r"(b0), "r"(b1))

__global__ __launch_bounds__(THREADS, 1)
void edge_kernel(const float* __restrict__ nf,
                 const float* __restrict__ esh,
                 const float* __restrict__ emb,
                 const float* __restrict__ w1,
                 const float* __restrict__ b1,
                 const float* __restrict__ w2,
                 const float* __restrict__ b2,
                 const int*   __restrict__ eidx)
{
    extern __shared__ __align__(1024) char sm[];
    const uint32_t sbase = smem_u32(sm);

    const int t = threadIdx.x;
    const int wid = t >> 5, lid = t & 31;
    const int qd = blockIdx.x & 3;           // v-quarter role 0..3

    float* sC   = (float*)(sm + SM_C);
    float* sXT  = (float*)(sm + SM_XT);
    float* sEmb = (float*)(sm + SM_EMB);
    float* sW1  = (float*)(sm + SM_W1);
    float* sB1  = (float*)(sm + SM_B1);
    float* sB2P = (float*)(sm + SM_B2P);
    float* sSH  = (float*)(sm + SM_SH);
    int*   sSrc = (int*)(sm + SM_SRC);
    int*   sDst = (int*)(sm + SM_DST);

    // ---- one-time staging ----
    // B physical row p = b*64 + vl*16 + u  ->  w2 col n = b*256 + u*16 + (qd*4+vl)
    for (int idx = t; idx < 64 * 256; idx += THREADS) {
        int k = idx >> 8, p = idx & 255;
        int b = p >> 6, vl = (p >> 4) & 3, u = p & 15;
        int n = b * 256 + u * 16 + qd * 4 + vl;
        float w = w2[k * 1024 + n];
        uint32_t off = SW128((uint32_t)(p * 128 + k * 2));
        *(__half*)(sm + SM_BH + off) = __float2half(w);
    }
    if (t < 256) {
        int p = t;
        int b = p >> 6, vl = (p >> 4) & 3, u = p & 15;
        sB2P[p] = b2[b * 256 + u * 16 + qd * 4 + vl];
    }
    for (int i = t; i < 1024; i += THREADS) sW1[i] = w1[i];
    if (t < 64) sB1[t] = b1[t];
    __syncthreads();

    const float ALPHA = 0.17677669529663687f;   // 1/sqrt(2*16)
    const float INV3  = 0.5773502691896258f;    // 1/sqrt(3)

    // MMA warp tiling: warp tile 32e x (32p per chunk, both chunks)
    const int wy = wid & 3;                    // e block
    const int wx = wid >> 2;                   // p block within chunk
    const int mi = lid >> 3, r = lid & 7;
    const int a_row_base = wy * 32 + ((mi & 1) << 3) + r;
    const uint32_t a_kb = (uint32_t)((mi >> 1) << 4);
    const int b_row_off = ((mi >> 1) << 3) + r;
    const uint32_t b_kb = (uint32_t)((mi & 1) << 4);
    const uint32_t lmask = (uint32_t)(r << 4);
    const int gid = lid >> 2, tid4 = lid & 3;

    // contraction mapping: e = t&127, vl = t>>7
    const int ce = t & 127;
    const int cvl = t >> 7;

    for (int tile = blockIdx.x >> 2; tile < EE / TE; tile += 37) {
        const int e0 = tile * TE;

        // ---- phase 0: stage edge meta (overlaps prior tile's reg-only scatter) ----
        if (t < 128)      sSrc[t] = eidx[e0 + t];
        else if (t < 256) sDst[t - 128] = eidx[EE + e0 + (t - 128)];
        sSH[t] = esh[e0 * 4 + t];
        #pragma unroll
        for (int rr = 0; rr < 4; ++rr) sEmb[t + rr * THREADS] = emb[e0 * 16 + t + rr * THREADS];
        __syncthreads();                                   // barA

        const int dst = sDst[ce];
        const float sh0 = sSH[ce * 4 + 0], sh1 = sSH[ce * 4 + 1];
        const float sh2 = sSH[ce * 4 + 2], sh3 = sSH[ce * 4 + 3];

        // ---- phase 1a: stage x vectors ----
        // row<16: xs[u]; row>=16: xv[u][i] at row 16 + i*16 + u
        {
            int e = t >> 2, q4 = t & 3;
            int src = sSrc[e];
            #pragma unroll
            for (int b = 0; b < 4; ++b) {
                float4 x4 = *(const float4*)(nf + src * 64 + q4 * 16 + b * 4);
                float vals[4] = {x4.x, x4.y, x4.z, x4.w};
                #pragma unroll
                for (int j = 0; j < 4; ++j) {
                    int m = q4 * 16 + b * 4 + j;           // 0..63
                    int row;
                    if (m < 16) row = m;
                    else { int mm = m - 16; row = 16 + (mm % 3) * 16 + (mm / 3); }
                    sXT[row * 128 + e] = vals[j];
                }
            }
        }

        // ---- phase 1b: H = silu(emb@w1+b1) -> fp16 A tile (SW128) ----
        #pragma unroll
        for (int rr = 0; rr < 8; ++rr) {
            int task = t + rr * THREADS;            // 4096 = 128e x 32 j-pairs
            int e = task >> 5, jp = task & 31;
            const float* er = sEmb + e * 16;
            float a0 = sB1[2 * jp], a1 = sB1[2 * jp + 1];
            #pragma unroll
            for (int k = 0; k < 16; ++k) {
                float ev = er[k];
                float2 wv = *(const float2*)(sW1 + k * 64 + 2 * jp);
                a0 += ev * wv.x;
                a1 += ev * wv.y;
            }
            float h0 = a0 / (1.0f + __expf(-a0));
            float h1 = a1 / (1.0f + __expf(-a1));
            __half2 hh = __floats2half2_rn(h0, h1);
            uint32_t off = SW128((uint32_t)(e * 128 + jp * 4));
            *(uint32_t*)(sm + SM_AH + off) = *(uint32_t*)&hh;
        }
        __syncthreads();                                   // barB

        // ---- MMA: both 128-col chunks in one phase ----
        float acc[2][2][4][4];                             // [chunk][m][nt][frag]
        #pragma unroll
        for (int ch = 0; ch < 2; ++ch)
            #pragma unroll
            for (int m = 0; m < 2; ++m)
                #pragma unroll
                for (int nt = 0; nt < 4; ++nt)
                    #pragma unroll
                    for (int z = 0; z < 4; ++z) acc[ch][m][nt][z] = 0.0f;

        #pragma unroll
        for (int ks = 0; ks < 4; ++ks) {
            const uint32_t kx = (uint32_t)(ks * 32);
            uint32_t ah[2][4], bh[2][2][4];
            #pragma unroll
            for (int m = 0; m < 2; ++m) {
                uint32_t row = (uint32_t)(a_row_base + m * 16);
                uint32_t ad = sbase + SM_AH + row * 128 + ((kx + a_kb) ^ lmask);
                LDSM4(ah[m][0], ah[m][1], ah[m][2], ah[m][3], ad);
            }
            #pragma unroll
            for (int ch = 0; ch < 2; ++ch)
                #pragma unroll
                for (int pr = 0; pr < 2; ++pr) {
                    uint32_t p = (uint32_t)(ch * 128 + wx * 32 + pr * 16 + b_row_off);
                    uint32_t bd = sbase + SM_BH + p * 128 + ((kx + b_kb) ^ lmask);
                    LDSM4(bh[ch][pr][0], bh[ch][pr][1], bh[ch][pr][2], bh[ch][pr][3], bd);
                }
            #pragma unroll
            for (int ch = 0; ch < 2; ++ch)
                #pragma unroll
                for (int m = 0; m < 2; ++m)
                    #pragma unroll
                    for (int pr = 0; pr < 2; ++pr)
                        #pragma unroll
                        for (int sb = 0; sb < 2; ++sb)
                            MMA16816(acc[ch][m][pr * 2 + sb], ah[m],
                                     bh[ch][pr][sb * 2], bh[ch][pr][sb * 2 + 1]);
        }

        // ---- store C + bias to smem (padded rows, both chunks) ----
        #pragma unroll
        for (int ch = 0; ch < 2; ++ch)
            #pragma unroll
            for (int m = 0; m < 2; ++m)
                #pragma unroll
                for (int nt = 0; nt < 4; ++nt) {
                    int colp = ch * 128 + wx * 32 + nt * 8 + tid4 * 2;
                    float b0 = sB2P[colp], b1v = sB2P[colp + 1];
                    int row0 = wy * 32 + m * 16 + gid;
                    float2 v01 = make_float2(acc[ch][m][nt][0] + b0, acc[ch][m][nt][1] + b1v);
                    float2 v23 = make_float2(acc[ch][m][nt][2] + b0, acc[ch][m][nt][3] + b1v);
                    *(float2*)&sC[row0 * CPAD + colp] = v01;
                    *(float2*)&sC[(row0 + 8) * CPAD + colp] = v23;
                }
        __syncthreads();                                   // barC

        // ---- contraction (all four W-blocks) + reg-only scatter ----
        {
            const float* base = sC + ce * CPAD + cvl * 16;
            float y00 = 0.0f, y01 = 0.0f;
            float z10_0 = 0.0f, z10_1 = 0.0f, z10_2 = 0.0f;
            float z11_0 = 0.0f, z11_1 = 0.0f, z11_2 = 0.0f;
            #pragma unroll
            for (int u = 0; u < 16; ++u) {
                float xs = sXT[u * 128 + ce];
                y00 += xs * base[u];
                y01 += xs * base[64 + u];
                float w10 = base[128 + u], w11 = base[192 + u];
                float x0 = sXT[(16 + 0 * 16 + u) * 128 + ce];
                float x1 = sXT[(16 + 1 * 16 + u) * 128 + ce];
                float x2 = sXT[(16 + 2 * 16 + u) * 128 + ce];
                z10_0 += x0 * w10;  z11_0 += x0 * w11;
                z10_1 += x1 * w10;  z11_1 += x1 * w11;
                z10_2 += x2 * w10;  z11_2 += x2 * w11;
            }
            int v = qd * 4 + cvl;
            float msg_s = ALPHA * (sh0 * y00 + INV3 * (sh1 * z11_0 + sh2 * z11_1 + sh3 * z11_2));
            atomicAdd(&g_agg[dst * 64 + v], msg_s);
            atomicAdd(&g_agg[dst * 64 + 16 + v * 3 + 0], ALPHA * (y01 * sh1 + sh0 * z10_0));
            atomicAdd(&g_agg[dst * 64 + 16 + v * 3 + 1], ALPHA * (y01 * sh2 + sh0 * z10_1));
            atomicAdd(&g_agg[dst * 64 + 16 + v * 3 + 2], ALPHA * (y01 * sh3 + sh0 * z10_2));
        }
        // no trailing barrier: scatter is reg-only; next tile's phase-0/1a smem writes
        // only touch regions whose last readers have passed a barrier (barA gates 1a).
    }
}

__global__ __launch_bounds__(256)
void node_kernel(const float* __restrict__ nf,
                 const float* __restrict__ lw0,
                 const float* __restrict__ lw1,
                 float* __restrict__ out)
{
    __shared__ float sw0[256], sw1[256];
    int t = threadIdx.x;
    sw0[t] = lw0[t];
    sw1[t] = lw1[t];
    __syncthreads();

    int node = blockIdx.x * 16 + (t >> 4);
    int v = t & 15;
    float* a = g_agg + node * 64;

    float ts = 0.0f, t0 = 0.0f, t1 = 0.0f, t2 = 0.0f;
    #pragma unroll
    for (int u = 0; u < 16; ++u) {
        float c0 = sw0[u * 16 + v];
        float c1 = sw1[u * 16 + v];
        ts += a[u] * c0;
        t0 += a[16 + u * 3 + 0] * c1;
        t1 += a[16 + u * 3 + 1] * c1;
        t2 += a[16 + u * 3 + 2] * c1;
    }
    __syncthreads();   // all threads of this block done reading these 16 nodes
    // re-zero for the next graph replay (g_agg starts zeroed at module load)
    a[v] = 0.0f;
    a[16 + v * 3 + 0] = 0.0f;
    a[16 + v * 3 + 1] = 0.0f;
    a[16 + v * 3 + 2] = 0.0f;

    const float S = 0.25f, EPS = 1e-8f;
    ts *= S; t0 *= S; t1 *= S; t2 *= S;

    float ns = fabsf(ts);
    float gs = ns / ((ns + EPS) * (1.0f + __expf(-ns)));
    float nv = sqrtf(t0 * t0 + t1 * t1 + t2 * t2);
    float gv = nv / ((nv + EPS) * (1.0f + __expf(-nv)));

    int base = node * 64;
    out[base + v] = nf[base + v] + ts * gs;
    out[base + 16 + v * 3 + 0] = nf[base + 16 + v * 3 + 0] + t0 * gv;
    out[base + 16 + v * 3 + 1] = nf[base + 16 + v * 3 + 1] + t1 * gv;
    out[base + 16 + v * 3 + 2] = nf[base + 16 + v * 3 + 2] + t2 * gv;
}

extern "C" void kernel_launch(void* const* d_in, const int* in_sizes, int n_in,
                              void* d_out, int out_size)
{
    const float* nf   = (const float*)d_in[0];
    const float* esh  = (const float*)d_in[1];
    const float* emb  = (const float*)d_in[2];
    const float* w1   = (const float*)d_in[3];
    const float* b1   = (const float*)d_in[4];
    const float* w2   = (const float*)d_in[5];
    const float* b2   = (const float*)d_in[6];
    const float* lw0  = (const float*)d_in[7];
    const float* lw1  = (const float*)d_in[8];
    const int*   eidx = (const int*)d_in[9];
    float* out = (float*)d_out;

    cudaFuncSetAttribute(edge_kernel, cudaFuncAttributeMaxDynamicSharedMemorySize, SMEM_TOTAL);

    // g_agg: zeroed at module load; node_kernel re-zeros after reading each call.
    edge_kernel<<<148, THREADS, SMEM_TOTAL>>>(nf, esh, emb, w1, b1, w2, b2, eidx);
    node_kernel<<<625, 256>>>(nf, lw0, lw1, out);
}

// round 15
// speedup vs baseline: 1.7331x; 1.1120x over previous
#include <cuda_runtime.h>
#include <cuda_fp16.h>
#include <cstdint>
#include <math.h>

#define NN 10000
#define EE 160000
#define TE 128
#define THREADS 512

// ---- shared memory byte offsets ----
#define SM_BH  0         // 256 rows x 64 fp16 (128B rows), SW128
#define SM_AH  32768     // 128 rows x 64 fp16 (128B rows), SW128
#define SM_C   49152     // 128 x 260 fp32 (padded rows) = 133120B
#define SM_XT  182272    // 64 x 128 fp32 = 32768B
#define SM_EMB 215040    // 128 x 16 fp32 = 8192B
#define SM_W1  223232    // 16 x 64 fp32 = 4096B
#define SM_B1  227328    // 64 fp32
#define SM_B2P 227584    // 256 fp32 (permuted bias)
#define SM_SH  228608    // 128 x 4 fp32
#define SM_SRC 230656    // 128 int
#define SM_DST 231168    // 128 int
#define SMEM_TOTAL 231680

#define SW128(x) ((x) ^ (((x) >> 3) & 0x70))
#define CPAD 260

// agg layout: [node][80] = 16 msg_s + 16 x (3 msg_v + 1 pad), 16B-aligned v-slots
__device__ float g_agg[NN * 80];

static __device__ __forceinline__ uint32_t smem_u32(const void* p) {
    uint32_t a;
    asm("{ .reg .u64 t; cvta.to.shared.u64 t, %1; cvt.u32.u64 %0, t; }" : "=r"(a) : "l"(p));
    return a;
}

#define LDSM4(r0, r1, r2, r3, addr) \
    asm volatile("ldmatrix.sync.aligned.m8n8.x4.shared.b16 {%0,%1,%2,%3}, [%4];" \
                 : "=r"(r0), "=r"(r1), "=r"(r2), "=r"(r3) : "r"(addr))

#define MMA16816(d, a, b0, b1) \
    asm volatile("mma.sync.aligned.m16n8k16.row.col.f32.f16.f16.f32 " \
                 "{%0,%1,%2,%3}, {%4,%5,%6,%7}, {%8,%9}, {%0,%1,%2,%3};" \
                 : "+f"((d)[0]), "+f"((d)[1]), "+f"((d)[2]), "+f"((d)[3]) \
                 : "r"((a)[0]), "r"((a)[1]), "r"((a)[2]), "r"((a)[3]), "r"(b0), "r"(b1))

__global__ __launch_bounds__(THREADS, 1)
void edge_kernel(const float* __restrict__ nf,
                 const float* __restrict__ esh,
                 const float* __restrict__ emb,
                 const float* __restrict__ w1,
                 const float* __restrict__ b1,
                 const float* __restrict__ w2,
                 const float* __restrict__ b2,
                 const int*   __restrict__ eidx)
{
    extern __shared__ __align__(1024) char sm[];
    const uint32_t sbase = smem_u32(sm);

    const int t = threadIdx.x;
    const int wid = t >> 5, lid = t & 31;
    const int qd = blockIdx.x & 3;           // v-quarter role 0..3

    float* sC   = (float*)(sm + SM_C);
    float* sXT  = (float*)(sm + SM_XT);
    float* sEmb = (float*)(sm + SM_EMB);
    float* sW1  = (float*)(sm + SM_W1);
    float* sB1  = (float*)(sm + SM_B1);
    float* sB2P = (float*)(sm + SM_B2P);
    float* sSH  = (float*)(sm + SM_SH);
    int*   sSrc = (int*)(sm + SM_SRC);
    int*   sDst = (int*)(sm + SM_DST);

    // ---- one-time staging ----
    // B physical row p = b*64 + vl*16 + u  ->  w2 col n = b*256 + u*16 + (qd*4+vl)
    for (int idx = t; idx < 64 * 256; idx += THREADS) {
        int k = idx >> 8, p = idx & 255;
        int b = p >> 6, vl = (p >> 4) & 3, u = p & 15;
        int n = b * 256 + u * 16 + qd * 4 + vl;
        float w = w2[k * 1024 + n];
        uint32_t off = SW128((uint32_t)(p * 128 + k * 2));
        *(__half*)(sm + SM_BH + off) = __float2half(w);
    }
    if (t < 256) {
        int p = t;
        int b = p >> 6, vl = (p >> 4) & 3, u = p & 15;
        sB2P[p] = b2[b * 256 + u * 16 + qd * 4 + vl];
    }
    for (int i = t; i < 1024; i += THREADS) sW1[i] = w1[i];
    if (t < 64) sB1[t] = b1[t];
    __syncthreads();

    const float ALPHA = 0.17677669529663687f;   // 1/sqrt(2*16)
    const float INV3  = 0.5773502691896258f;    // 1/sqrt(3)

    // MMA warp tiling: warp tile 32e x (32p per chunk, both chunks)
    const int wy = wid & 3;                    // e block
    const int wx = wid >> 2;                   // p block within chunk
    const int mi = lid >> 3, r = lid & 7;
    const int a_row_base = wy * 32 + ((mi & 1) << 3) + r;
    const uint32_t a_kb = (uint32_t)((mi >> 1) << 4);
    const int b_row_off = ((mi >> 1) << 3) + r;
    const uint32_t b_kb = (uint32_t)((mi & 1) << 4);
    const uint32_t lmask = (uint32_t)(r << 4);
    const int gid = lid >> 2, tid4 = lid & 3;

    // contraction mapping: e = t&127, vl = t>>7
    const int ce = t & 127;
    const int cvl = t >> 7;

    // ---- prefetch first tile's meta into registers ----
    int   pf_idx = 0;
    float pf_sh = 0.0f;
    float pf_emb[4];
    {
        const int tile = blockIdx.x >> 2;
        const int e0 = tile * TE;
        if (t < 128)      pf_idx = eidx[e0 + t];
        else if (t < 256) pf_idx = eidx[EE + e0 + (t - 128)];
        pf_sh = esh[e0 * 4 + t];
        #pragma unroll
        for (int rr = 0; rr < 4; ++rr) pf_emb[rr] = emb[e0 * 16 + t + rr * THREADS];
    }

    for (int tile = blockIdx.x >> 2; tile < EE / TE; tile += 37) {
        // ---- phase 0: commit prefetched meta to smem ----
        if (t < 128)      sSrc[t] = pf_idx;
        else if (t < 256) sDst[t - 128] = pf_idx;
        sSH[t] = pf_sh;
        #pragma unroll
        for (int rr = 0; rr < 4; ++rr) sEmb[t + rr * THREADS] = pf_emb[rr];
        __syncthreads();                                   // barA

        const int dst = sDst[ce];
        const float sh0 = sSH[ce * 4 + 0], sh1 = sSH[ce * 4 + 1];
        const float sh2 = sSH[ce * 4 + 2], sh3 = sSH[ce * 4 + 3];

        // ---- phase 1a: stage x vectors ----
        // row<16: xs[u]; row>=16: xv[u][i] at row 16 + i*16 + u
        {
            int e = t >> 2, q4 = t & 3;
            int src = sSrc[e];
            #pragma unroll
            for (int b = 0; b < 4; ++b) {
                float4 x4 = *(const float4*)(nf + src * 64 + q4 * 16 + b * 4);
                float vals[4] = {x4.x, x4.y, x4.z, x4.w};
                #pragma unroll
                for (int j = 0; j < 4; ++j) {
                    int m = q4 * 16 + b * 4 + j;           // 0..63
                    int row;
                    if (m < 16) row = m;
                    else { int mm = m - 16; row = 16 + (mm % 3) * 16 + (mm / 3); }
                    sXT[row * 128 + e] = vals[j];
                }
            }
        }

        // ---- phase 1b: H = silu(emb@w1+b1) -> fp16 A tile (SW128) ----
        #pragma unroll
        for (int rr = 0; rr < 8; ++rr) {
            int task = t + rr * THREADS;            // 4096 = 128e x 32 j-pairs
            int e = task >> 5, jp = task & 31;
            const float* er = sEmb + e * 16;
            float a0 = sB1[2 * jp], a1 = sB1[2 * jp + 1];
            #pragma unroll
            for (int k = 0; k < 16; ++k) {
                float ev = er[k];
                float2 wv = *(const float2*)(sW1 + k * 64 + 2 * jp);
                a0 += ev * wv.x;
                a1 += ev * wv.y;
            }
            float h0 = a0 / (1.0f + __expf(-a0));
            float h1 = a1 / (1.0f + __expf(-a1));
            __half2 hh = __floats2half2_rn(h0, h1);
            uint32_t off = SW128((uint32_t)(e * 128 + jp * 4));
            *(uint32_t*)(sm + SM_AH + off) = *(uint32_t*)&hh;
        }
        __syncthreads();                                   // barB

        // ---- MMA: both 128-col chunks in one phase ----
        float acc[2][2][4][4];                             // [chunk][m][nt][frag]
        #pragma unroll
        for (int ch = 0; ch < 2; ++ch)
            #pragma unroll
            for (int m = 0; m < 2; ++m)
                #pragma unroll
                for (int nt = 0; nt < 4; ++nt)
                    #pragma unroll
                    for (int z = 0; z < 4; ++z) acc[ch][m][nt][z] = 0.0f;

        #pragma unroll
        for (int ks = 0; ks < 4; ++ks) {
            const uint32_t kx = (uint32_t)(ks * 32);
            uint32_t ah[2][4], bh[2][2][4];
            #pragma unroll
            for (int m = 0; m < 2; ++m) {
                uint32_t row = (uint32_t)(a_row_base + m * 16);
                uint32_t ad = sbase + SM_AH + row * 128 + ((kx + a_kb) ^ lmask);
                LDSM4(ah[m][0], ah[m][1], ah[m][2], ah[m][3], ad);
            }
            #pragma unroll
            for (int ch = 0; ch < 2; ++ch)
                #pragma unroll
                for (int pr = 0; pr < 2; ++pr) {
                    uint32_t p = (uint32_t)(ch * 128 + wx * 32 + pr * 16 + b_row_off);
                    uint32_t bd = sbase + SM_BH + p * 128 + ((kx + b_kb) ^ lmask);
                    LDSM4(bh[ch][pr][0], bh[ch][pr][1], bh[ch][pr][2], bh[ch][pr][3], bd);
                }
            #pragma unroll
            for (int ch = 0; ch < 2; ++ch)
                #pragma unroll
                for (int m = 0; m < 2; ++m)
                    #pragma unroll
                    for (int pr = 0; pr < 2; ++pr)
                        #pragma unroll
                        for (int sb = 0; sb < 2; ++sb)
                            MMA16816(acc[ch][m][pr * 2 + sb], ah[m],
                                     bh[ch][pr][sb * 2], bh[ch][pr][sb * 2 + 1]);
        }

        // ---- store C + bias to smem (padded rows, both chunks) ----
        #pragma unroll
        for (int ch = 0; ch < 2; ++ch)
            #pragma unroll
            for (int m = 0; m < 2; ++m)
                #pragma unroll
                for (int nt = 0; nt < 4; ++nt) {
                    int colp = ch * 128 + wx * 32 + nt * 8 + tid4 * 2;
                    float b0 = sB2P[colp], b1v = sB2P[colp + 1];
                    int row0 = wy * 32 + m * 16 + gid;
                    float2 v01 = make_float2(acc[ch][m][nt][0] + b0, acc[ch][m][nt][1] + b1v);
                    float2 v23 = make_float2(acc[ch][m][nt][2] + b0, acc[ch][m][nt][3] + b1v);
                    *(float2*)&sC[row0 * CPAD + colp] = v01;
                    *(float2*)&sC[(row0 + 8) * CPAD + colp] = v23;
                }
        __syncthreads();                                   // barC

        // ---- prefetch next tile's meta (hidden under contraction) ----
        {
            int ntile = tile + 37;
            if (ntile < EE / TE) {
                int e0n = ntile * TE;
                if (t < 128)      pf_idx = eidx[e0n + t];
                else if (t < 256) pf_idx = eidx[EE + e0n + (t - 128)];
                pf_sh = esh[e0n * 4 + t];
                #pragma unroll
                for (int rr = 0; rr < 4; ++rr) pf_emb[rr] = emb[e0n * 16 + t + rr * THREADS];
            }
        }

        // ---- contraction (float4 C reads) + vectorized scatter ----
        {
            const float* base = sC + ce * CPAD + cvl * 16;
            float y00 = 0.0f, y01 = 0.0f;
            float z10_0 = 0.0f, z10_1 = 0.0f, z10_2 = 0.0f;
            float z11_0 = 0.0f, z11_1 = 0.0f, z11_2 = 0.0f;
            #pragma unroll
            for (int j = 0; j < 4; ++j) {
                float4 c0 = *(const float4*)(base + j * 4);          // W00
                float4 c1 = *(const float4*)(base + 64 + j * 4);     // W01
                float4 c2 = *(const float4*)(base + 128 + j * 4);    // W10
                float4 c3 = *(const float4*)(base + 192 + j * 4);    // W11
                float c0a[4] = {c0.x, c0.y, c0.z, c0.w};
                float c1a[4] = {c1.x, c1.y, c1.z, c1.w};
                float c2a[4] = {c2.x, c2.y, c2.z, c2.w};
                float c3a[4] = {c3.x, c3.y, c3.z, c3.w};
                #pragma unroll
                for (int k = 0; k < 4; ++k) {
                    int u = j * 4 + k;
                    float xs = sXT[u * 128 + ce];
                    y00 += xs * c0a[k];
                    y01 += xs * c1a[k];
                    float w10 = c2a[k], w11 = c3a[k];
                    float x0 = sXT[(16 + 0 * 16 + u) * 128 + ce];
                    float x1 = sXT[(16 + 1 * 16 + u) * 128 + ce];
                    float x2 = sXT[(16 + 2 * 16 + u) * 128 + ce];
                    z10_0 += x0 * w10;  z11_0 += x0 * w11;
                    z10_1 += x1 * w10;  z11_1 += x1 * w11;
                    z10_2 += x2 * w10;  z11_2 += x2 * w11;
                }
            }
            int v = qd * 4 + cvl;
            float msg_s = ALPHA * (sh0 * y00 + INV3 * (sh1 * z11_0 + sh2 * z11_1 + sh3 * z11_2));
            atomicAdd(&g_agg[dst * 80 + v], msg_s);
            float4 mv = make_float4(ALPHA * (y01 * sh1 + sh0 * z10_0),
                                    ALPHA * (y01 * sh2 + sh0 * z10_1),
                                    ALPHA * (y01 * sh3 + sh0 * z10_2),
                                    0.0f);
            atomicAdd((float4*)&g_agg[dst * 80 + 16 + v * 4], mv);
        }
        // no trailing barrier: scatter is reg-only; next phase-0 smem writes are safe
    }
}

__global__ __launch_bounds__(256)
void node_kernel(const float* __restrict__ nf,
                 const float* __restrict__ lw0,
                 const float* __restrict__ lw1,
                 float* __restrict__ out)
{
    __shared__ float sw0[256], sw1[256];
    int t = threadIdx.x;
    sw0[t] = lw0[t];
    sw1[t] = lw1[t];
    __syncthreads();

    int node = blockIdx.x * 16 + (t >> 4);
    int v = t & 15;
    float* a = g_agg + node * 80;

    float ts = 0.0f, t0 = 0.0f, t1 = 0.0f, t2 = 0.0f;
    #pragma unroll
    for (int u = 0; u < 16; ++u) {
        float c0 = sw0[u * 16 + v];
        float c1 = sw1[u * 16 + v];
        ts += a[u] * c0;
        t0 += a[16 + u * 4 + 0] * c1;
        t1 += a[16 + u * 4 + 1] * c1;
        t2 += a[16 + u * 4 + 2] * c1;
    }
    __syncthreads();   // all threads of this block done reading these 16 nodes
    // re-zero for the next graph replay (g_agg starts zeroed at module load)
    a[v] = 0.0f;
    *(float4*)&a[16 + v * 4] = make_float4(0.0f, 0.0f, 0.0f, 0.0f);

    const float S = 0.25f, EPS = 1e-8f;
    ts *= S; t0 *= S; t1 *= S; t2 *= S;

    float ns = fabsf(ts);
    float gs = ns / ((ns + EPS) * (1.0f + __expf(-ns)));
    float nv = sqrtf(t0 * t0 + t1 * t1 + t2 * t2);
    float gv = nv / ((nv + EPS) * (1.0f + __expf(-nv)));

    int base = node * 64;
    out[base + v] = nf[base + v] + ts * gs;
    out[base + 16 + v * 3 + 0] = nf[base + 16 + v * 3 + 0] + t0 * gv;
    out[base + 16 + v * 3 + 1] = nf[base + 16 + v * 3 + 1] + t1 * gv;
    out[base + 16 + v * 3 + 2] = nf[base + 16 + v * 3 + 2] + t2 * gv;
}

extern "C" void kernel_launch(void* const* d_in, const int* in_sizes, int n_in,
                              void* d_out, int out_size)
{
    const float* nf   = (const float*)d_in[0];
    const float* esh  = (const float*)d_in[1];
    const float* emb  = (const float*)d_in[2];
    const float* w1   = (const float*)d_in[3];
    const float* b1   = (const float*)d_in[4];
    const float* w2   = (const float*)d_in[5];
    const float* b2   = (const float*)d_in[6];
    const float* lw0  = (const float*)d_in[7];
    const float* lw1  = (const float*)d_in[8];
    const int*   eidx = (const int*)d_in[9];
    float* out = (float*)d_out;

    cudaFuncSetAttribute(edge_kernel, cudaFuncAttributeMaxDynamicSharedMemorySize, SMEM_TOTAL);

    // g_agg: zeroed at module load; node_kernel re-zeros after reading each call.
    edge_kernel<<<148, THREADS, SMEM_TOTAL>>>(nf, esh, emb, w1, b1, w2, b2, eidx);
    node_kernel<<<625, 256>>>(nf, lw0, lw1, out);
}